// round 2
// baseline (speedup 1.0000x reference)
#include <cuda_runtime.h>
#include <math.h>

// ---------------------------------------------------------------------------
// SelfAttention (B=4, S=1024, D=4096, HQ=32, HKV=8, HD=128, start_pos=0,
// non-causal). GEMMs: 3xTF32 mma.sync (near-fp32 accuracy). Attn: fp32 flash.
// ---------------------------------------------------------------------------

// Scratch (device globals; allocation in kernel_launch is forbidden)
__device__ float g_q[16777216];   // [4096][4096]
__device__ float g_k[4194304];    // [4096][1024]
__device__ float g_v[4194304];    // [4096][1024]
__device__ float g_attn[16777216];// [4096][4096]

// ---------------------------------------------------------------------------
// 3xTF32 helpers
// ---------------------------------------------------------------------------
__device__ __forceinline__ unsigned f2tf32(float x) {
    unsigned u;
    asm("cvt.rna.tf32.f32 %0, %1;" : "=r"(u) : "f"(x));
    return u;
}

__device__ __forceinline__ void mma_tf32(float c[4],
                                         unsigned a0, unsigned a1,
                                         unsigned a2, unsigned a3,
                                         unsigned b0, unsigned b1)
{
    asm volatile(
        "mma.sync.aligned.m16n8k8.row.col.f32.tf32.tf32.f32 "
        "{%0,%1,%2,%3}, {%4,%5,%6,%7}, {%8,%9}, {%0,%1,%2,%3};"
        : "+f"(c[0]), "+f"(c[1]), "+f"(c[2]), "+f"(c[3])
        : "r"(a0), "r"(a1), "r"(a2), "r"(a3), "r"(b0), "r"(b1));
}

// ---------------------------------------------------------------------------
// C[M,N] = A[M,K] * B[N,K]^T  (row-major, K contiguous) via 3xTF32.
// Block 128x128, BK=16, 8 warps; warp tile 32(M)x64(N) of m16n8k8.
// smem k-major, stride 136 -> fragment LDS bank = 8*tg+g (conflict-free).
// M,N multiples of 128; K multiple of 16 (holds for all 4 GEMMs here).
// ---------------------------------------------------------------------------
#define GLDS 136

__global__ __launch_bounds__(256, 1)
void gemm_tf32x3(const float* __restrict__ A, const float* __restrict__ B,
                 float* __restrict__ C, int M, int N, int K)
{
    __shared__ unsigned Ah[16][GLDS], Al[16][GLDS];
    __shared__ unsigned Bh[16][GLDS], Bl[16][GLDS];

    const int tid  = threadIdx.x;
    const int bm   = blockIdx.y * 128;
    const int bn   = blockIdx.x * 128;
    const int wid  = tid >> 5;
    const int lane = tid & 31;
    const int g    = lane >> 2;     // 0..7
    const int tg   = lane & 3;      // 0..3
    const int wm   = (wid >> 1) * 32;   // 0,32,64,96
    const int wn   = (wid & 1) * 64;    // 0,64

    // global->smem mapping: thread covers rows lr, lr+64 at k cols lk..lk+3
    const int lr = tid >> 2;        // 0..63
    const int lk = (tid & 3) * 4;   // 0,4,8,12

    float acc[2][8][4];
#pragma unroll
    for (int mi = 0; mi < 2; mi++)
#pragma unroll
        for (int ni = 0; ni < 8; ni++)
#pragma unroll
            for (int j = 0; j < 4; j++) acc[mi][ni][j] = 0.f;

    for (int k0 = 0; k0 < K; k0 += 16) {
#pragma unroll
        for (int rr = 0; rr < 2; rr++) {
            int row = lr + rr * 64;
            float4 va = *(const float4*)(A + (size_t)(bm + row) * K + k0 + lk);
            float4 vb = *(const float4*)(B + (size_t)(bn + row) * K + k0 + lk);
            float fa[4] = {va.x, va.y, va.z, va.w};
            float fb[4] = {vb.x, vb.y, vb.z, vb.w};
#pragma unroll
            for (int j = 0; j < 4; j++) {
                unsigned h = f2tf32(fa[j]);
                Ah[lk + j][row] = h;
                Al[lk + j][row] = f2tf32(fa[j] - __uint_as_float(h));
                unsigned hб = f2tf32(fb[j]);
                Bh[lk + j][row] = hб;
                Bl[lk + j][row] = f2tf32(fb[j] - __uint_as_float(hб));
            }
        }
        __syncthreads();

#pragma unroll
        for (int ks = 0; ks < 2; ks++) {
            const int kb = ks * 8;
            unsigned ah[2][4], al[2][4];
#pragma unroll
            for (int mi = 0; mi < 2; mi++) {
                int r0 = wm + mi * 16;
                ah[mi][0] = Ah[kb + tg][r0 + g];
                ah[mi][1] = Ah[kb + tg][r0 + g + 8];
                ah[mi][2] = Ah[kb + tg + 4][r0 + g];
                ah[mi][3] = Ah[kb + tg + 4][r0 + g + 8];
                al[mi][0] = Al[kb + tg][r0 + g];
                al[mi][1] = Al[kb + tg][r0 + g + 8];
                al[mi][2] = Al[kb + tg + 4][r0 + g];
                al[mi][3] = Al[kb + tg + 4][r0 + g + 8];
            }
            unsigned bh[8][2], bl[8][2];
#pragma unroll
            for (int ni = 0; ni < 8; ni++) {
                int c0 = wn + ni * 8;
                bh[ni][0] = Bh[kb + tg][c0 + g];
                bh[ni][1] = Bh[kb + tg + 4][c0 + g];
                bl[ni][0] = Bl[kb + tg][c0 + g];
                bl[ni][1] = Bl[kb + tg + 4][c0 + g];
            }
#pragma unroll
            for (int mi = 0; mi < 2; mi++)
#pragma unroll
                for (int ni = 0; ni < 8; ni++) {
                    // (ah+al)*(bh+bl) ~= al*bh + ah*bl + ah*bh
                    mma_tf32(acc[mi][ni], al[mi][0], al[mi][1], al[mi][2], al[mi][3],
                             bh[ni][0], bh[ni][1]);
                    mma_tf32(acc[mi][ni], ah[mi][0], ah[mi][1], ah[mi][2], ah[mi][3],
                             bl[ni][0], bl[ni][1]);
                    mma_tf32(acc[mi][ni], ah[mi][0], ah[mi][1], ah[mi][2], ah[mi][3],
                             bh[ni][0], bh[ni][1]);
                }
        }
        __syncthreads();
    }

    // store: c0=(g,2tg) c1=(g,2tg+1) c2=(g+8,2tg) c3=(g+8,2tg+1)
#pragma unroll
    for (int mi = 0; mi < 2; mi++) {
        int r0 = bm + wm + mi * 16 + g;
#pragma unroll
        for (int ni = 0; ni < 8; ni++) {
            int c = bn + wn + ni * 8 + tg * 2;
            *(float2*)(C + (size_t)r0 * N + c) =
                make_float2(acc[mi][ni][0], acc[mi][ni][1]);
            *(float2*)(C + (size_t)(r0 + 8) * N + c) =
                make_float2(acc[mi][ni][2], acc[mi][ni][3]);
        }
    }
}

// ---------------------------------------------------------------------------
// RoPE in-place on buf[4096 rows][nh*128]
// ---------------------------------------------------------------------------
__global__ void rope_kernel(float* __restrict__ buf, int nh,
                            const float* __restrict__ cosb,
                            const float* __restrict__ sinb)
{
    int idx = blockIdx.x * blockDim.x + threadIdx.x;
    int total = 4096 * nh * 64;
    if (idx >= total) return;
    int i   = idx & 63;
    int t   = idx >> 6;
    int h   = t % nh;
    int row = t / nh;
    int s   = row & 1023;
    float c  = cosb[s*64 + i];
    float sn = sinb[s*64 + i];
    float2* p = (float2*)(buf + (size_t)row * (nh*128) + h*128 + 2*i);
    float2 v = *p;
    float2 o;
    o.x = v.x * c - v.y * sn;
    o.y = v.x * sn + v.y * c;
    *p = o;
}

// ---------------------------------------------------------------------------
// Flash attention (non-causal, 1024 keys), fp32 SIMT (same as round-1 design)
// ---------------------------------------------------------------------------
__global__ __launch_bounds__(256)
void attn_kernel(const float* __restrict__ Q, const float* __restrict__ Kb,
                 const float* __restrict__ Vb, float* __restrict__ O)
{
    extern __shared__ float sm[];
    float* Qs  = sm;                      // [64][128] pre-scaled
    float* KVs = sm + 64*128;             // K^T [128][32] then V [32][128]
    float* Ps  = sm + 64*128 + 32*128;    // [64][32]

    const int tid = threadIdx.x;
    const int qt  = blockIdx.x;
    const int h   = blockIdx.y;
    const int b   = blockIdx.z;
    const int kvh = h >> 2;
    const int ty  = tid >> 4;
    const int tx  = tid & 15;
    const float scale = 0.08838834764831845f;

    const float* Qg = Q + ((size_t)(b*1024 + qt*64)) * 4096 + h*128;
    for (int i = tid; i < 64*32; i += 256) {
        int r = i >> 5, c = i & 31;
        float4 v = *(const float4*)(Qg + (size_t)r*4096 + c*4);
        v.x *= scale; v.y *= scale; v.z *= scale; v.w *= scale;
        ((float4*)Qs)[r*32 + c] = v;
    }

    float m[4], l[4], acc[4][8];
#pragma unroll
    for (int i = 0; i < 4; i++) {
        m[i] = -1e30f; l[i] = 0.f;
#pragma unroll
        for (int j = 0; j < 8; j++) acc[i][j] = 0.f;
    }

    for (int kt = 0; kt < 32; kt++) {
        __syncthreads();

        const float* Kg = Kb + ((size_t)(b*1024 + kt*32)) * 1024 + kvh*128;
        for (int i = tid; i < 32*32; i += 256) {
            int key = i >> 5, c = i & 31;
            float4 v = *(const float4*)(Kg + (size_t)key*1024 + c*4);
            KVs[(c*4+0)*32 + key] = v.x;
            KVs[(c*4+1)*32 + key] = v.y;
            KVs[(c*4+2)*32 + key] = v.z;
            KVs[(c*4+3)*32 + key] = v.w;
        }
        __syncthreads();

        float s[4][2];
#pragma unroll
        for (int i = 0; i < 4; i++) { s[i][0] = 0.f; s[i][1] = 0.f; }
        for (int kk = 0; kk < 128; kk++) {
            float k0 = KVs[kk*32 + tx];
            float k1 = KVs[kk*32 + tx + 16];
#pragma unroll
            for (int i = 0; i < 4; i++) {
                float qv = Qs[(ty*4+i)*128 + kk];
                s[i][0] += qv * k0;
                s[i][1] += qv * k1;
            }
        }

#pragma unroll
        for (int i = 0; i < 4; i++) {
            float mx = fmaxf(s[i][0], s[i][1]);
#pragma unroll
            for (int off = 8; off; off >>= 1)
                mx = fmaxf(mx, __shfl_xor_sync(0xffffffffu, mx, off, 16));
            float mnew = fmaxf(m[i], mx);
            float corr = __expf(m[i] - mnew);
            float p0 = __expf(s[i][0] - mnew);
            float p1 = __expf(s[i][1] - mnew);
            float ps = p0 + p1;
#pragma unroll
            for (int off = 8; off; off >>= 1)
                ps += __shfl_xor_sync(0xffffffffu, ps, off, 16);
            m[i] = mnew;
            l[i] = l[i] * corr + ps;
#pragma unroll
            for (int j = 0; j < 8; j++) acc[i][j] *= corr;
            Ps[(ty*4+i)*32 + tx]      = p0;
            Ps[(ty*4+i)*32 + tx + 16] = p1;
        }
        __syncthreads();

        const float* Vg = Vb + ((size_t)(b*1024 + kt*32)) * 1024 + kvh*128;
        for (int i = tid; i < 32*32; i += 256) {
            int r = i >> 5, c = i & 31;
            ((float4*)KVs)[r*32 + c] = *(const float4*)(Vg + (size_t)r*1024 + c*4);
        }
        __syncthreads();

#pragma unroll 4
        for (int k = 0; k < 32; k++) {
            float4 v0 = *(const float4*)&KVs[k*128 + tx*8];
            float4 v1 = *(const float4*)&KVs[k*128 + tx*8 + 4];
#pragma unroll
            for (int i = 0; i < 4; i++) {
                float p = Ps[(ty*4+i)*32 + k];
                acc[i][0] += p*v0.x; acc[i][1] += p*v0.y;
                acc[i][2] += p*v0.z; acc[i][3] += p*v0.w;
                acc[i][4] += p*v1.x; acc[i][5] += p*v1.y;
                acc[i][6] += p*v1.z; acc[i][7] += p*v1.w;
            }
        }
    }

    float* Og = O + ((size_t)(b*1024 + qt*64)) * 4096 + h*128;
#pragma unroll
    for (int i = 0; i < 4; i++) {
        float inv = 1.f / l[i];
        float* op = Og + (size_t)(ty*4+i)*4096 + tx*8;
        *(float4*)(op)   = make_float4(acc[i][0]*inv, acc[i][1]*inv,
                                       acc[i][2]*inv, acc[i][3]*inv);
        *(float4*)(op+4) = make_float4(acc[i][4]*inv, acc[i][5]*inv,
                                       acc[i][6]*inv, acc[i][7]*inv);
    }
}

// ---------------------------------------------------------------------------
// kernel_launch: x, wq, wk, wv, wo, freqs_cos, freqs_sin, cache_k, cache_v,
// start_pos (start_pos=0, caches zero -> only final output matters)
// ---------------------------------------------------------------------------
extern "C" void kernel_launch(void* const* d_in, const int* in_sizes, int n_in,
                              void* d_out, int out_size)
{
    const float* x  = (const float*)d_in[0];
    const float* wq = (const float*)d_in[1];
    const float* wk = (const float*)d_in[2];
    const float* wv = (const float*)d_in[3];
    const float* wo = (const float*)d_in[4];
    const float* fc = (const float*)d_in[5];
    const float* fs = (const float*)d_in[6];
    float* out = (float*)d_out;

    float *qb, *kb, *vb, *ab;
    cudaGetSymbolAddress((void**)&qb, g_q);
    cudaGetSymbolAddress((void**)&kb, g_k);
    cudaGetSymbolAddress((void**)&vb, g_v);
    cudaGetSymbolAddress((void**)&ab, g_attn);

    cudaFuncSetAttribute(attn_kernel,
                         cudaFuncAttributeMaxDynamicSharedMemorySize, 57344);

    dim3 blk(256);
    gemm_tf32x3<<<dim3(32, 32), blk>>>(x, wq, qb, 4096, 4096, 4096);
    gemm_tf32x3<<<dim3(8,  32), blk>>>(x, wk, kb, 4096, 1024, 4096);
    gemm_tf32x3<<<dim3(8,  32), blk>>>(x, wv, vb, 4096, 1024, 4096);
    rope_kernel<<<(4096*32*64 + 255)/256, 256>>>(qb, 32, fc, fs);
    rope_kernel<<<(4096*8*64  + 255)/256, 256>>>(kb, 8,  fc, fs);
    attn_kernel<<<dim3(16, 32, 4), 256, 57344>>>(qb, kb, vb, ab);
    gemm_tf32x3<<<dim3(32, 32), blk>>>(ab, wo, out, 4096, 4096, 4096);
}

// round 3
// speedup vs baseline: 1.1713x; 1.1713x over previous
#include <cuda_runtime.h>
#include <math.h>

// ---------------------------------------------------------------------------
// SelfAttention (B=4, S=1024, D=4096, HQ=32, HKV=8, HD=128, start_pos=0,
// non-causal). GEMMs: 3xTF32 mma.sync with cp.async double-buffered pipeline.
// Attn: fp32 flash.
// ---------------------------------------------------------------------------

__device__ float g_q[16777216];   // [4096][4096]
__device__ float g_k[4194304];    // [4096][1024]
__device__ float g_v[4194304];    // [4096][1024]
__device__ float g_attn[16777216];// [4096][4096]

__device__ __forceinline__ unsigned f2tf32(float x) {
    unsigned u;
    asm("cvt.rna.tf32.f32 %0, %1;" : "=r"(u) : "f"(x));
    return u;
}

__device__ __forceinline__ void mma_tf32(float c[4],
                                         unsigned a0, unsigned a1,
                                         unsigned a2, unsigned a3,
                                         unsigned b0, unsigned b1)
{
    asm volatile(
        "mma.sync.aligned.m16n8k8.row.col.f32.tf32.tf32.f32 "
        "{%0,%1,%2,%3}, {%4,%5,%6,%7}, {%8,%9}, {%0,%1,%2,%3};"
        : "+f"(c[0]), "+f"(c[1]), "+f"(c[2]), "+f"(c[3])
        : "r"(a0), "r"(a1), "r"(a2), "r"(a3), "r"(b0), "r"(b1));
}

__device__ __forceinline__ unsigned smem_u32(const void* p) {
    return (unsigned)__cvta_generic_to_shared(p);
}
__device__ __forceinline__ void cp_async16(unsigned dst, const void* src) {
    asm volatile("cp.async.cg.shared.global [%0], [%1], 16;" :: "r"(dst), "l"(src));
}

// ---------------------------------------------------------------------------
// C[M,N] = A[M,K] * B[N,K]^T (row-major, K contiguous) via 3xTF32 mma.sync.
// Block 128x128, BK=16, 8 warps, warp tile 32x64 of m16n8k8.
// Raw fp32 staged in smem via cp.async (2 stages); hi/lo tf32 split at
// fragment-load time. Row stride 20 floats: 16B-aligned rows AND
// conflict-free fragment loads (bank = (20g+tg) mod 32, all distinct).
// ---------------------------------------------------------------------------
#define BK   16
#define RSTR 20   // floats per smem row (16 data + 4 pad)

__global__ __launch_bounds__(256, 1)
void gemm_tf32x3(const float* __restrict__ A, const float* __restrict__ B,
                 float* __restrict__ C, int M, int N, int K)
{
    __shared__ float As[2][128 * RSTR];
    __shared__ float Bs[2][128 * RSTR];

    const int tid  = threadIdx.x;
    const int bm   = blockIdx.y * 128;
    const int bn   = blockIdx.x * 128;
    const int wid  = tid >> 5;
    const int lane = tid & 31;
    const int g    = lane >> 2;       // 0..7
    const int tg   = lane & 3;        // 0..3
    const int wm   = (wid >> 1) * 32; // 0,32,64,96
    const int wn   = (wid & 1) * 64;  // 0,64

    // global->smem: thread owns row lr, k cols [lk, lk+8)
    const int lr = tid >> 1;          // 0..127
    const int lk = (tid & 1) * 8;     // 0 or 8

    const float* Ag = A + (size_t)(bm + lr) * K + lk;
    const float* Bg = B + (size_t)(bn + lr) * K + lk;

    unsigned dA0[2], dA1[2], dB0[2], dB1[2];
#pragma unroll
    for (int st = 0; st < 2; st++) {
        dA0[st] = smem_u32(&As[st][lr * RSTR + lk]);
        dA1[st] = dA0[st] + 16;
        dB0[st] = smem_u32(&Bs[st][lr * RSTR + lk]);
        dB1[st] = dB0[st] + 16;
    }

    float acc[2][8][4];
#pragma unroll
    for (int mi = 0; mi < 2; mi++)
#pragma unroll
        for (int ni = 0; ni < 8; ni++)
#pragma unroll
            for (int j = 0; j < 4; j++) acc[mi][ni][j] = 0.f;

    const int nIter = K / BK;

    // prologue: stage 0
    cp_async16(dA0[0], Ag);
    cp_async16(dA1[0], Ag + 4);
    cp_async16(dB0[0], Bg);
    cp_async16(dB1[0], Bg + 4);
    asm volatile("cp.async.commit_group;");

    for (int it = 0; it < nIter; it++) {
        asm volatile("cp.async.wait_group 0;");
        __syncthreads();

        if (it + 1 < nIter) {
            const int st = (it + 1) & 1;
            const int k0 = (it + 1) * BK;
            cp_async16(dA0[st], Ag + k0);
            cp_async16(dA1[st], Ag + k0 + 4);
            cp_async16(dB0[st], Bg + k0);
            cp_async16(dB1[st], Bg + k0 + 4);
            asm volatile("cp.async.commit_group;");
        }

        const float* Ab = As[it & 1];
        const float* Bb = Bs[it & 1];

#pragma unroll
        for (int ks = 0; ks < 2; ks++) {
            const int kb = ks * 8;
            unsigned ah[2][4], al[2][4];
#pragma unroll
            for (int mi = 0; mi < 2; mi++) {
                const int r0 = wm + mi * 16;
                float r[4];
                r[0] = Ab[(r0 + g)     * RSTR + kb + tg];
                r[1] = Ab[(r0 + g + 8) * RSTR + kb + tg];
                r[2] = Ab[(r0 + g)     * RSTR + kb + tg + 4];
                r[3] = Ab[(r0 + g + 8) * RSTR + kb + tg + 4];
#pragma unroll
                for (int j = 0; j < 4; j++) {
                    unsigned h = f2tf32(r[j]);
                    ah[mi][j] = h;
                    al[mi][j] = f2tf32(r[j] - __uint_as_float(h));
                }
            }
            unsigned bh[8][2], bl[8][2];
#pragma unroll
            for (int ni = 0; ni < 8; ni++) {
                const int c0 = wn + ni * 8;
                float r0f = Bb[(c0 + g) * RSTR + kb + tg];
                float r1f = Bb[(c0 + g) * RSTR + kb + tg + 4];
                unsigned h0 = f2tf32(r0f);
                unsigned h1 = f2tf32(r1f);
                bh[ni][0] = h0;
                bh[ni][1] = h1;
                bl[ni][0] = f2tf32(r0f - __uint_as_float(h0));
                bl[ni][1] = f2tf32(r1f - __uint_as_float(h1));
            }
#pragma unroll
            for (int mi = 0; mi < 2; mi++)
#pragma unroll
                for (int ni = 0; ni < 8; ni++) {
                    // (ah+al)(bh+bl) ~= al*bh + ah*bl + ah*bh
                    mma_tf32(acc[mi][ni], al[mi][0], al[mi][1], al[mi][2], al[mi][3],
                             bh[ni][0], bh[ni][1]);
                    mma_tf32(acc[mi][ni], ah[mi][0], ah[mi][1], ah[mi][2], ah[mi][3],
                             bl[ni][0], bl[ni][1]);
                    mma_tf32(acc[mi][ni], ah[mi][0], ah[mi][1], ah[mi][2], ah[mi][3],
                             bh[ni][0], bh[ni][1]);
                }
        }
    }

    // store: c0=(g,2tg) c1=(g,2tg+1) c2=(g+8,2tg) c3=(g+8,2tg+1)
#pragma unroll
    for (int mi = 0; mi < 2; mi++) {
        const int r0 = bm + wm + mi * 16 + g;
#pragma unroll
        for (int ni = 0; ni < 8; ni++) {
            const int c = bn + wn + ni * 8 + tg * 2;
            *(float2*)(C + (size_t)r0 * N + c) =
                make_float2(acc[mi][ni][0], acc[mi][ni][1]);
            *(float2*)(C + (size_t)(r0 + 8) * N + c) =
                make_float2(acc[mi][ni][2], acc[mi][ni][3]);
        }
    }
}

// ---------------------------------------------------------------------------
// RoPE in-place on buf[4096 rows][nh*128]
// ---------------------------------------------------------------------------
__global__ void rope_kernel(float* __restrict__ buf, int nh,
                            const float* __restrict__ cosb,
                            const float* __restrict__ sinb)
{
    int idx = blockIdx.x * blockDim.x + threadIdx.x;
    int total = 4096 * nh * 64;
    if (idx >= total) return;
    int i   = idx & 63;
    int t   = idx >> 6;
    int h   = t % nh;
    int row = t / nh;
    int s   = row & 1023;
    float c  = cosb[s*64 + i];
    float sn = sinb[s*64 + i];
    float2* p = (float2*)(buf + (size_t)row * (nh*128) + h*128 + 2*i);
    float2 v = *p;
    float2 o;
    o.x = v.x * c - v.y * sn;
    o.y = v.x * sn + v.y * c;
    *p = o;
}

// ---------------------------------------------------------------------------
// Flash attention (non-causal, 1024 keys), fp32 SIMT
// ---------------------------------------------------------------------------
__global__ __launch_bounds__(256)
void attn_kernel(const float* __restrict__ Q, const float* __restrict__ Kb,
                 const float* __restrict__ Vb, float* __restrict__ O)
{
    extern __shared__ float sm[];
    float* Qs  = sm;                      // [64][128] pre-scaled
    float* KVs = sm + 64*128;             // K^T [128][32] then V [32][128]
    float* Ps  = sm + 64*128 + 32*128;    // [64][32]

    const int tid = threadIdx.x;
    const int qt  = blockIdx.x;
    const int h   = blockIdx.y;
    const int b   = blockIdx.z;
    const int kvh = h >> 2;
    const int ty  = tid >> 4;
    const int tx  = tid & 15;
    const float scale = 0.08838834764831845f;

    const float* Qg = Q + ((size_t)(b*1024 + qt*64)) * 4096 + h*128;
    for (int i = tid; i < 64*32; i += 256) {
        int r = i >> 5, c = i & 31;
        float4 v = *(const float4*)(Qg + (size_t)r*4096 + c*4);
        v.x *= scale; v.y *= scale; v.z *= scale; v.w *= scale;
        ((float4*)Qs)[r*32 + c] = v;
    }

    float m[4], l[4], acc[4][8];
#pragma unroll
    for (int i = 0; i < 4; i++) {
        m[i] = -1e30f; l[i] = 0.f;
#pragma unroll
        for (int j = 0; j < 8; j++) acc[i][j] = 0.f;
    }

    for (int kt = 0; kt < 32; kt++) {
        __syncthreads();

        const float* Kg = Kb + ((size_t)(b*1024 + kt*32)) * 1024 + kvh*128;
        for (int i = tid; i < 32*32; i += 256) {
            int key = i >> 5, c = i & 31;
            float4 v = *(const float4*)(Kg + (size_t)key*1024 + c*4);
            KVs[(c*4+0)*32 + key] = v.x;
            KVs[(c*4+1)*32 + key] = v.y;
            KVs[(c*4+2)*32 + key] = v.z;
            KVs[(c*4+3)*32 + key] = v.w;
        }
        __syncthreads();

        float s[4][2];
#pragma unroll
        for (int i = 0; i < 4; i++) { s[i][0] = 0.f; s[i][1] = 0.f; }
        for (int kk = 0; kk < 128; kk++) {
            float k0 = KVs[kk*32 + tx];
            float k1 = KVs[kk*32 + tx + 16];
#pragma unroll
            for (int i = 0; i < 4; i++) {
                float qv = Qs[(ty*4+i)*128 + kk];
                s[i][0] += qv * k0;
                s[i][1] += qv * k1;
            }
        }

#pragma unroll
        for (int i = 0; i < 4; i++) {
            float mx = fmaxf(s[i][0], s[i][1]);
#pragma unroll
            for (int off = 8; off; off >>= 1)
                mx = fmaxf(mx, __shfl_xor_sync(0xffffffffu, mx, off, 16));
            float mnew = fmaxf(m[i], mx);
            float corr = __expf(m[i] - mnew);
            float p0 = __expf(s[i][0] - mnew);
            float p1 = __expf(s[i][1] - mnew);
            float ps = p0 + p1;
#pragma unroll
            for (int off = 8; off; off >>= 1)
                ps += __shfl_xor_sync(0xffffffffu, ps, off, 16);
            m[i] = mnew;
            l[i] = l[i] * corr + ps;
#pragma unroll
            for (int j = 0; j < 8; j++) acc[i][j] *= corr;
            Ps[(ty*4+i)*32 + tx]      = p0;
            Ps[(ty*4+i)*32 + tx + 16] = p1;
        }
        __syncthreads();

        const float* Vg = Vb + ((size_t)(b*1024 + kt*32)) * 1024 + kvh*128;
        for (int i = tid; i < 32*32; i += 256) {
            int r = i >> 5, c = i & 31;
            ((float4*)KVs)[r*32 + c] = *(const float4*)(Vg + (size_t)r*1024 + c*4);
        }
        __syncthreads();

#pragma unroll 4
        for (int k = 0; k < 32; k++) {
            float4 v0 = *(const float4*)&KVs[k*128 + tx*8];
            float4 v1 = *(const float4*)&KVs[k*128 + tx*8 + 4];
#pragma unroll
            for (int i = 0; i < 4; i++) {
                float p = Ps[(ty*4+i)*32 + k];
                acc[i][0] += p*v0.x; acc[i][1] += p*v0.y;
                acc[i][2] += p*v0.z; acc[i][3] += p*v0.w;
                acc[i][4] += p*v1.x; acc[i][5] += p*v1.y;
                acc[i][6] += p*v1.z; acc[i][7] += p*v1.w;
            }
        }
    }

    float* Og = O + ((size_t)(b*1024 + qt*64)) * 4096 + h*128;
#pragma unroll
    for (int i = 0; i < 4; i++) {
        float inv = 1.f / l[i];
        float* op = Og + (size_t)(ty*4+i)*4096 + tx*8;
        *(float4*)(op)   = make_float4(acc[i][0]*inv, acc[i][1]*inv,
                                       acc[i][2]*inv, acc[i][3]*inv);
        *(float4*)(op+4) = make_float4(acc[i][4]*inv, acc[i][5]*inv,
                                       acc[i][6]*inv, acc[i][7]*inv);
    }
}

// ---------------------------------------------------------------------------
extern "C" void kernel_launch(void* const* d_in, const int* in_sizes, int n_in,
                              void* d_out, int out_size)
{
    const float* x  = (const float*)d_in[0];
    const float* wq = (const float*)d_in[1];
    const float* wk = (const float*)d_in[2];
    const float* wv = (const float*)d_in[3];
    const float* wo = (const float*)d_in[4];
    const float* fc = (const float*)d_in[5];
    const float* fs = (const float*)d_in[6];
    float* out = (float*)d_out;

    float *qb, *kb, *vb, *ab;
    cudaGetSymbolAddress((void**)&qb, g_q);
    cudaGetSymbolAddress((void**)&kb, g_k);
    cudaGetSymbolAddress((void**)&vb, g_v);
    cudaGetSymbolAddress((void**)&ab, g_attn);

    cudaFuncSetAttribute(attn_kernel,
                         cudaFuncAttributeMaxDynamicSharedMemorySize, 57344);

    dim3 blk(256);
    gemm_tf32x3<<<dim3(32, 32), blk>>>(x, wq, qb, 4096, 4096, 4096);
    gemm_tf32x3<<<dim3(8,  32), blk>>>(x, wk, kb, 4096, 1024, 4096);
    gemm_tf32x3<<<dim3(8,  32), blk>>>(x, wv, vb, 4096, 1024, 4096);
    rope_kernel<<<(4096*32*64 + 255)/256, 256>>>(qb, 32, fc, fs);
    rope_kernel<<<(4096*8*64  + 255)/256, 256>>>(kb, 8,  fc, fs);
    attn_kernel<<<dim3(16, 32, 4), 256, 57344>>>(qb, kb, vb, ab);
    gemm_tf32x3<<<dim3(32, 32), blk>>>(ab, wo, out, 4096, 4096, 4096);
}

// round 8
// speedup vs baseline: 1.7974x; 1.5346x over previous
#include <cuda_runtime.h>
#include <cuda_fp16.h>
#include <math.h>

// ---------------------------------------------------------------------------
// SelfAttention (B=4, S=1024, D=4096, HQ=32, HKV=8, HD=128, start_pos=0,
// non-causal). GEMMs: fp16x2-split (3 HMMA passes, ~tf32x3 accuracy) with
// 4-stage cp.async pipeline. Attn: fp32 flash, epilogue emits fp16 planes.
// ---------------------------------------------------------------------------

// fp32 intermediates
__device__ float g_q[16777216];   // [4096][4096]
__device__ float g_k[4194304];    // [4096][1024]
__device__ float g_v[4194304];    // [4096][1024]
// fp16 hi/lo planes
__device__ __half g_xh[16777216],  g_xl[16777216];
__device__ __half g_wqh[16777216], g_wql[16777216];
__device__ __half g_wkh[4194304],  g_wkl[4194304];
__device__ __half g_wvh[4194304],  g_wvl[4194304];
__device__ __half g_woh[16777216], g_wol[16777216];
__device__ __half g_ah[16777216],  g_al[16777216];   // attention output planes

__device__ __forceinline__ unsigned smem_u32(const void* p) {
    return (unsigned)__cvta_generic_to_shared(p);
}
__device__ __forceinline__ void cp_async16(unsigned dst, const void* src) {
    asm volatile("cp.async.cg.shared.global [%0], [%1], 16;" :: "r"(dst), "l"(src));
}

__device__ __forceinline__ void mma_f16(float c[4], const unsigned a[4],
                                        const unsigned b[2])
{
    asm volatile(
        "mma.sync.aligned.m16n8k16.row.col.f32.f16.f16.f32 "
        "{%0,%1,%2,%3}, {%4,%5,%6,%7}, {%8,%9}, {%0,%1,%2,%3};"
        : "+f"(c[0]), "+f"(c[1]), "+f"(c[2]), "+f"(c[3])
        : "r"(a[0]), "r"(a[1]), "r"(a[2]), "r"(a[3]), "r"(b[0]), "r"(b[1]));
}

// ---------------------------------------------------------------------------
// split: fp32 -> (hi fp16, lo fp16), lo = rn(x - hi). n4 = n/4.
// ---------------------------------------------------------------------------
__global__ void split_f16(const float* __restrict__ src,
                          __half* __restrict__ hi, __half* __restrict__ lo,
                          int n4)
{
    int i = blockIdx.x * blockDim.x + threadIdx.x;
    if (i >= n4) return;
    float4 v = ((const float4*)src)[i];
    float f[4] = {v.x, v.y, v.z, v.w};
    __half h[4], l[4];
#pragma unroll
    for (int j = 0; j < 4; j++) {
        h[j] = __float2half_rn(f[j]);
        l[j] = __float2half_rn(f[j] - __half2float(h[j]));
    }
    ((__half2*)hi)[i*2]   = __halves2half2(h[0], h[1]);
    ((__half2*)hi)[i*2+1] = __halves2half2(h[2], h[3]);
    ((__half2*)lo)[i*2]   = __halves2half2(l[0], l[1]);
    ((__half2*)lo)[i*2+1] = __halves2half2(l[2], l[3]);
}

// ---------------------------------------------------------------------------
// C[M,N] = A[M,K] * B[N,K]^T from fp16 hi/lo planes, 3 passes:
//   C = Al*Bh + Ah*Bl + Ah*Bh   (Al*Bl ~ 2^-22, dropped)
// Block 128x128, BK=16, 8 warps (warp tile 32x64 of m16n8k16), 4-stage
// cp.async pipeline. Smem rows: 16 halves data + 8 pad (48 B) -> 16B-aligned
// cp.async dst AND conflict-free LDS.32 fragments (word = 12g+tg, distinct).
// ---------------------------------------------------------------------------
#define HSTR    24                 // halves per smem row
#define PLANE_H (128*HSTR)         // halves per plane  (3072)
#define PLANE_B (PLANE_H*2)        // bytes per plane   (6144)
#define STAGE_B (4*PLANE_B)        // bytes per stage   (24576)
#define STAGE_H (4*PLANE_H)        // halves per stage  (12288)
#define NSTAGE  4

__global__ __launch_bounds__(256, 2)
void gemm_f16x3(const __half* __restrict__ Ahp, const __half* __restrict__ Alp,
                const __half* __restrict__ Bhp, const __half* __restrict__ Blp,
                float* __restrict__ C, int M, int N, int K)
{
    extern __shared__ __half sm[];

    const int tid  = threadIdx.x;
    const int bm   = blockIdx.y * 128;
    const int bn   = blockIdx.x * 128;
    const int wid  = tid >> 5;
    const int lane = tid & 31;
    const int g    = lane >> 2;        // 0..7
    const int tg   = lane & 3;         // 0..3
    const int wm   = (wid >> 1) * 32;  // 0,32,64,96
    const int wn   = (wid & 1) * 64;   // 0,64

    // copy mapping: thread owns row lr, 16B chunk lhalf (8 halves)
    const int lr    = tid >> 1;        // 0..127
    const int lhalf = tid & 1;         // 0,1

    const __half* srcAh = Ahp + (size_t)(bm + lr) * K + lhalf * 8;
    const __half* srcAl = Alp + (size_t)(bm + lr) * K + lhalf * 8;
    const __half* srcBh = Bhp + (size_t)(bn + lr) * K + lhalf * 8;
    const __half* srcBl = Blp + (size_t)(bn + lr) * K + lhalf * 8;

    const unsigned dbase = smem_u32(sm) + (lr * HSTR + lhalf * 8) * 2;

    float acc[2][8][4];
#pragma unroll
    for (int mi = 0; mi < 2; mi++)
#pragma unroll
        for (int ni = 0; ni < 8; ni++)
#pragma unroll
            for (int j = 0; j < 4; j++) acc[mi][ni][j] = 0.f;

    const int nIter = K / 16;

    // prologue: stages 0..2
#pragma unroll
    for (int st = 0; st < NSTAGE - 1; st++) {
        const unsigned d = dbase + st * STAGE_B;
        const int k0 = st * 16;
        cp_async16(d,               srcAh + k0);
        cp_async16(d + PLANE_B,     srcAl + k0);
        cp_async16(d + 2*PLANE_B,   srcBh + k0);
        cp_async16(d + 3*PLANE_B,   srcBl + k0);
        asm volatile("cp.async.commit_group;");
    }

    for (int it = 0; it < nIter; it++) {
        asm volatile("cp.async.wait_group %0;" :: "n"(NSTAGE - 2));
        __syncthreads();

        if (it + NSTAGE - 1 < nIter) {
            const int st = (it + NSTAGE - 1) % NSTAGE;
            const int k0 = (it + NSTAGE - 1) * 16;
            const unsigned d = dbase + st * STAGE_B;
            cp_async16(d,               srcAh + k0);
            cp_async16(d + PLANE_B,     srcAl + k0);
            cp_async16(d + 2*PLANE_B,   srcBh + k0);
            cp_async16(d + 3*PLANE_B,   srcBl + k0);
        }
        asm volatile("cp.async.commit_group;");   // always: keeps group math exact

        const __half* Ab_h = sm + (it % NSTAGE) * STAGE_H;
        const __half* Ab_l = Ab_h + PLANE_H;
        const __half* Bb_h = Ab_h + 2 * PLANE_H;
        const __half* Bb_l = Ab_h + 3 * PLANE_H;

        unsigned ah[2][4], al[2][4];
#pragma unroll
        for (int mi = 0; mi < 2; mi++) {
            const int r0 = wm + mi * 16;
            const __half* pah = Ab_h + (r0 + g) * HSTR + 2 * tg;
            const __half* pal = Ab_l + (r0 + g) * HSTR + 2 * tg;
            ah[mi][0] = *(const unsigned*)(pah);
            ah[mi][1] = *(const unsigned*)(pah + 8 * HSTR);
            ah[mi][2] = *(const unsigned*)(pah + 8);
            ah[mi][3] = *(const unsigned*)(pah + 8 * HSTR + 8);
            al[mi][0] = *(const unsigned*)(pal);
            al[mi][1] = *(const unsigned*)(pal + 8 * HSTR);
            al[mi][2] = *(const unsigned*)(pal + 8);
            al[mi][3] = *(const unsigned*)(pal + 8 * HSTR + 8);
        }
        unsigned bh[8][2], bl[8][2];
#pragma unroll
        for (int ni = 0; ni < 8; ni++) {
            const int c0 = wn + ni * 8;
            const __half* pbh = Bb_h + (c0 + g) * HSTR + 2 * tg;
            const __half* pbl = Bb_l + (c0 + g) * HSTR + 2 * tg;
            bh[ni][0] = *(const unsigned*)(pbh);
            bh[ni][1] = *(const unsigned*)(pbh + 8);
            bl[ni][0] = *(const unsigned*)(pbl);
            bl[ni][1] = *(const unsigned*)(pbl + 8);
        }
#pragma unroll
        for (int mi = 0; mi < 2; mi++)
#pragma unroll
            for (int ni = 0; ni < 8; ni++) {
                mma_f16(acc[mi][ni], al[mi], bh[ni]);
                mma_f16(acc[mi][ni], ah[mi], bl[ni]);
                mma_f16(acc[mi][ni], ah[mi], bh[ni]);
            }
    }

    // store: c0=(g,2tg) c1=(g,2tg+1) c2=(g+8,2tg) c3=(g+8,2tg+1)
#pragma unroll
    for (int mi = 0; mi < 2; mi++) {
        const int r0 = bm + wm + mi * 16 + g;
#pragma unroll
        for (int ni = 0; ni < 8; ni++) {
            const int c = bn + wn + ni * 8 + tg * 2;
            *(float2*)(C + (size_t)r0 * N + c) =
                make_float2(acc[mi][ni][0], acc[mi][ni][1]);
            *(float2*)(C + (size_t)(r0 + 8) * N + c) =
                make_float2(acc[mi][ni][2], acc[mi][ni][3]);
        }
    }
}

// ---------------------------------------------------------------------------
// RoPE in-place on buf[4096 rows][nh*128]
// ---------------------------------------------------------------------------
__global__ void rope_kernel(float* __restrict__ buf, int nh,
                            const float* __restrict__ cosb,
                            const float* __restrict__ sinb)
{
    int idx = blockIdx.x * blockDim.x + threadIdx.x;
    int total = 4096 * nh * 64;
    if (idx >= total) return;
    int i   = idx & 63;
    int t   = idx >> 6;
    int h   = t % nh;
    int row = t / nh;
    int s   = row & 1023;
    float c  = cosb[s*64 + i];
    float sn = sinb[s*64 + i];
    float2* p = (float2*)(buf + (size_t)row * (nh*128) + h*128 + 2*i);
    float2 v = *p;
    float2 o;
    o.x = v.x * c - v.y * sn;
    o.y = v.x * sn + v.y * c;
    *p = o;
}

// ---------------------------------------------------------------------------
// Flash attention (non-causal, 1024 keys), fp32 SIMT.
// Epilogue writes output directly as fp16 hi/lo planes for the WO GEMM.
// ---------------------------------------------------------------------------
__global__ __launch_bounds__(256)
void attn_kernel(const float* __restrict__ Q, const float* __restrict__ Kb,
                 const float* __restrict__ Vb,
                 __half* __restrict__ Oh, __half* __restrict__ Ol)
{
    extern __shared__ float smf[];
    float* Qs  = smf;                      // [64][128] pre-scaled
    float* KVs = smf + 64*128;             // K^T [128][32] then V [32][128]
    float* Ps  = smf + 64*128 + 32*128;    // [64][32]

    const int tid = threadIdx.x;
    const int qt  = blockIdx.x;
    const int h   = blockIdx.y;
    const int b   = blockIdx.z;
    const int kvh = h >> 2;
    const int ty  = tid >> 4;
    const int tx  = tid & 15;
    const float scale = 0.08838834764831845f;

    const float* Qg = Q + ((size_t)(b*1024 + qt*64)) * 4096 + h*128;
    for (int i = tid; i < 64*32; i += 256) {
        int r = i >> 5, c = i & 31;
        float4 v = *(const float4*)(Qg + (size_t)r*4096 + c*4);
        v.x *= scale; v.y *= scale; v.z *= scale; v.w *= scale;
        ((float4*)Qs)[r*32 + c] = v;
    }

    float m[4], l[4], acc[4][8];
#pragma unroll
    for (int i = 0; i < 4; i++) {
        m[i] = -1e30f; l[i] = 0.f;
#pragma unroll
        for (int j = 0; j < 8; j++) acc[i][j] = 0.f;
    }

    for (int kt = 0; kt < 32; kt++) {
        __syncthreads();

        const float* Kg = Kb + ((size_t)(b*1024 + kt*32)) * 1024 + kvh*128;
        for (int i = tid; i < 32*32; i += 256) {
            int key = i >> 5, c = i & 31;
            float4 v = *(const float4*)(Kg + (size_t)key*1024 + c*4);
            KVs[(c*4+0)*32 + key] = v.x;
            KVs[(c*4+1)*32 + key] = v.y;
            KVs[(c*4+2)*32 + key] = v.z;
            KVs[(c*4+3)*32 + key] = v.w;
        }
        __syncthreads();

        float s[4][2];
#pragma unroll
        for (int i = 0; i < 4; i++) { s[i][0] = 0.f; s[i][1] = 0.f; }
        for (int kk = 0; kk < 128; kk++) {
            float k0 = KVs[kk*32 + tx];
            float k1 = KVs[kk*32 + tx + 16];
#pragma unroll
            for (int i = 0; i < 4; i++) {
                float qv = Qs[(ty*4+i)*128 + kk];
                s[i][0] += qv * k0;
                s[i][1] += qv * k1;
            }
        }

#pragma unroll
        for (int i = 0; i < 4; i++) {
            float mx = fmaxf(s[i][0], s[i][1]);
#pragma unroll
            for (int off = 8; off; off >>= 1)
                mx = fmaxf(mx, __shfl_xor_sync(0xffffffffu, mx, off, 16));
            float mnew = fmaxf(m[i], mx);
            float corr = __expf(m[i] - mnew);
            float p0 = __expf(s[i][0] - mnew);
            float p1 = __expf(s[i][1] - mnew);
            float ps = p0 + p1;
#pragma unroll
            for (int off = 8; off; off >>= 1)
                ps += __shfl_xor_sync(0xffffffffu, ps, off, 16);
            m[i] = mnew;
            l[i] = l[i] * corr + ps;
#pragma unroll
            for (int j = 0; j < 8; j++) acc[i][j] *= corr;
            Ps[(ty*4+i)*32 + tx]      = p0;
            Ps[(ty*4+i)*32 + tx + 16] = p1;
        }
        __syncthreads();

        const float* Vg = Vb + ((size_t)(b*1024 + kt*32)) * 1024 + kvh*128;
        for (int i = tid; i < 32*32; i += 256) {
            int r = i >> 5, c = i & 31;
            ((float4*)KVs)[r*32 + c] = *(const float4*)(Vg + (size_t)r*1024 + c*4);
        }
        __syncthreads();

#pragma unroll 4
        for (int k = 0; k < 32; k++) {
            float4 v0 = *(const float4*)&KVs[k*128 + tx*8];
            float4 v1 = *(const float4*)&KVs[k*128 + tx*8 + 4];
#pragma unroll
            for (int i = 0; i < 4; i++) {
                float p = Ps[(ty*4+i)*32 + k];
                acc[i][0] += p*v0.x; acc[i][1] += p*v0.y;
                acc[i][2] += p*v0.z; acc[i][3] += p*v0.w;
                acc[i][4] += p*v1.x; acc[i][5] += p*v1.y;
                acc[i][6] += p*v1.z; acc[i][7] += p*v1.w;
            }
        }
    }

    // epilogue: fp16 hi/lo split planes
#pragma unroll
    for (int i = 0; i < 4; i++) {
        float inv = 1.f / l[i];
        size_t off = ((size_t)(b*1024 + qt*64 + ty*4 + i)) * 4096 + h*128 + tx*8;
        __align__(16) __half hh[8], ll[8];
#pragma unroll
        for (int j = 0; j < 8; j++) {
            float val = acc[i][j] * inv;
            hh[j] = __float2half_rn(val);
            ll[j] = __float2half_rn(val - __half2float(hh[j]));
        }
        *(uint4*)(Oh + off) = *(const uint4*)hh;
        *(uint4*)(Ol + off) = *(const uint4*)ll;
    }
}

// ---------------------------------------------------------------------------
extern "C" void kernel_launch(void* const* d_in, const int* in_sizes, int n_in,
                              void* d_out, int out_size)
{
    const float* x  = (const float*)d_in[0];
    const float* wq = (const float*)d_in[1];
    const float* wk = (const float*)d_in[2];
    const float* wv = (const float*)d_in[3];
    const float* wo = (const float*)d_in[4];
    const float* fc = (const float*)d_in[5];
    const float* fs = (const float*)d_in[6];
    float* out = (float*)d_out;

    float *qb, *kb, *vb;
    __half *xh, *xl, *wqh, *wql, *wkh, *wkl, *wvh, *wvl, *woh, *wol, *ahp, *alp;
    cudaGetSymbolAddress((void**)&qb, g_q);
    cudaGetSymbolAddress((void**)&kb, g_k);
    cudaGetSymbolAddress((void**)&vb, g_v);
    cudaGetSymbolAddress((void**)&xh, g_xh);   cudaGetSymbolAddress((void**)&xl, g_xl);
    cudaGetSymbolAddress((void**)&wqh, g_wqh); cudaGetSymbolAddress((void**)&wql, g_wql);
    cudaGetSymbolAddress((void**)&wkh, g_wkh); cudaGetSymbolAddress((void**)&wkl, g_wkl);
    cudaGetSymbolAddress((void**)&wvh, g_wvh); cudaGetSymbolAddress((void**)&wvl, g_wvl);
    cudaGetSymbolAddress((void**)&woh, g_woh); cudaGetSymbolAddress((void**)&wol, g_wol);
    cudaGetSymbolAddress((void**)&ahp, g_ah);  cudaGetSymbolAddress((void**)&alp, g_al);

    cudaFuncSetAttribute(gemm_f16x3,
                         cudaFuncAttributeMaxDynamicSharedMemorySize, NSTAGE*STAGE_B);
    cudaFuncSetAttribute(attn_kernel,
                         cudaFuncAttributeMaxDynamicSharedMemorySize, 57344);

    // split fp32 -> fp16 hi/lo planes
    split_f16<<<16384, 256>>>(x,  xh,  xl,  4194304);
    split_f16<<<16384, 256>>>(wq, wqh, wql, 4194304);
    split_f16<<<4096,  256>>>(wk, wkh, wkl, 1048576);
    split_f16<<<4096,  256>>>(wv, wvh, wvl, 1048576);
    split_f16<<<16384, 256>>>(wo, woh, wol, 4194304);

    dim3 blk(256);
    gemm_f16x3<<<dim3(32, 32), blk, NSTAGE*STAGE_B>>>(xh, xl, wqh, wql, qb, 4096, 4096, 4096);
    gemm_f16x3<<<dim3(8,  32), blk, NSTAGE*STAGE_B>>>(xh, xl, wkh, wkl, kb, 4096, 1024, 4096);
    gemm_f16x3<<<dim3(8,  32), blk, NSTAGE*STAGE_B>>>(xh, xl, wvh, wvl, vb, 4096, 1024, 4096);

    rope_kernel<<<(4096*32*64 + 255)/256, 256>>>(qb, 32, fc, fs);
    rope_kernel<<<(4096*8*64  + 255)/256, 256>>>(kb, 8,  fc, fs);

    attn_kernel<<<dim3(16, 32, 4), 256, 57344>>>(qb, kb, vb, ahp, alp);

    gemm_f16x3<<<dim3(32, 32), blk, NSTAGE*STAGE_B>>>(ahp, alp, woh, wol, out, 4096, 4096, 4096);
}